// round 1
// baseline (speedup 1.0000x reference)
#include <cuda_runtime.h>
#include <math.h>

// ---------------------------------------------------------------------------
// MultiHeadAttention (B=8, T=1024, E=768, H=12) -- fp32 baseline
//
// Stage 0: Q/K/V[h] = x @ W{Q,K,V}[h]          (36 GEMMs 8192x768x768)
// Stage 1: S[h,b]   = Q[h,b] @ view(K[h,b])    (96 GEMMs 1024x1024x768, ldb=1024)
// Stage 2: column softmax of S (axis = query), scale 1/32 folded in
// Stage 3: Z[b][h]  = S[h,b] @ V[h,b]          (96 GEMMs 1024x768x1024)
//          stored [b][h][t][v] so that...
// Stage 4: out      = view(Z, 8192x9216) @ WO  (1 GEMM 8192x768x9216)
// ---------------------------------------------------------------------------

// scratch (device globals; allocation-free per harness rules)
__device__ float g_Q[12 * 8 * 1024 * 768];   // [h][b][t][k]
__device__ float g_K[12 * 8 * 1024 * 768];   // [h][b][t][k]
__device__ float g_V[12 * 8 * 1024 * 768];   // [h][b][t][v]
__device__ float g_S[12 * 8 * 1024 * 1024];  // [h*8+b][t][t]
__device__ float g_Z[8 * 12 * 1024 * 768];   // [b][h][t][v]

#define BM 128
#define BN 128
#define BK 8

__global__ __launch_bounds__(256, 2)
void gemm_kernel(int mode,
                 const float* __restrict__ x,
                 const float* __restrict__ WQ,
                 const float* __restrict__ WK,
                 const float* __restrict__ WV,
                 const float* __restrict__ WO,
                 float* __restrict__ out)
{
    const float* A;
    const float* B;
    float* C;
    int lda, ldb, ldc, K;
    const int z = blockIdx.z;

    if (mode == 0) {
        // projections: z = which*12 + h ; which 0=Q,1=K,2=V
        int which = z / 12;
        int h = z - which * 12;
        A = x;  lda = 768;  K = 768;
        const float* Wb = (which == 0) ? WQ : (which == 1) ? WK : WV;
        B = Wb + h * 589824;  ldb = 768;                 // 768*768
        float* Ob = (which == 0) ? g_Q : (which == 1) ? g_K : g_V;
        C = Ob + h * 6291456; ldc = 768;                 // 8192*768
    } else if (mode == 1) {
        // scores: z = h*8+b.  B is K's buffer viewed as (768 x 1024) row-major.
        A = g_Q + z * 786432; lda = 768;  K = 768;
        B = g_K + z * 786432; ldb = 1024;
        C = g_S + z * 1048576; ldc = 1024;
    } else if (mode == 2) {
        // Z = A @ V, written into [b][h][t][v] layout
        int h = z >> 3, b = z & 7;
        A = g_S + z * 1048576; lda = 1024; K = 1024;
        B = g_V + z * 786432;  ldb = 768;
        C = g_Z + b * 9437184 + h * 786432; ldc = 768;   // 12*1024*768 per batch
    } else {
        // out = view(Z) @ WO
        A = g_Z; lda = 9216; K = 9216;
        B = WO;  ldb = 768;
        C = out; ldc = 768;
    }

    __shared__ float As[2][BK][BM];
    __shared__ float Bs[2][BK][BN];

    const int tid  = threadIdx.x;
    const int row0 = blockIdx.y * BM;
    const int col0 = blockIdx.x * BN;

    // global-load mapping
    const int arow = tid >> 1;           // 0..127
    const int acol = (tid & 1) << 2;     // 0 or 4
    const int brow = tid >> 5;           // 0..7
    const int bcol = (tid & 31) << 2;    // 0..124

    const float* Aptr = A + (row0 + arow) * lda + acol;
    const float* Bptr = B + brow * ldb + col0 + bcol;

    // compute mapping: 16x16 threads of 8x8 each
    const int rowb = (tid >> 4) << 3;    // 0..120
    const int colb = (tid & 15) << 3;    // 0..120

    float acc[8][8];
#pragma unroll
    for (int i = 0; i < 8; i++)
#pragma unroll
        for (int j = 0; j < 8; j++) acc[i][j] = 0.0f;

    // prologue: stage k-block 0
    float4 a4 = *(const float4*)(Aptr);
    float4 b4 = *(const float4*)(Bptr);
    As[0][acol + 0][arow] = a4.x;
    As[0][acol + 1][arow] = a4.y;
    As[0][acol + 2][arow] = a4.z;
    As[0][acol + 3][arow] = a4.w;
    *(float4*)&Bs[0][brow][bcol] = b4;
    __syncthreads();

    const int nIter = K / BK;
    for (int it = 0; it < nIter; ++it) {
        const int cur = it & 1;
        const bool more = (it + 1) < nIter;
        if (more) {  // issue next global loads early; latency hides under FMAs
            a4 = *(const float4*)(Aptr + (it + 1) * BK);
            b4 = *(const float4*)(Bptr + (it + 1) * BK * ldb);
        }
#pragma unroll
        for (int kk = 0; kk < BK; ++kk) {
            float ar[8], br[8];
            *(float4*)&ar[0] = *(const float4*)&As[cur][kk][rowb];
            *(float4*)&ar[4] = *(const float4*)&As[cur][kk][rowb + 4];
            *(float4*)&br[0] = *(const float4*)&Bs[cur][kk][colb];
            *(float4*)&br[4] = *(const float4*)&Bs[cur][kk][colb + 4];
#pragma unroll
            for (int i = 0; i < 8; i++)
#pragma unroll
                for (int j = 0; j < 8; j++)
                    acc[i][j] += ar[i] * br[j];
        }
        if (more) {
            const int nxt = cur ^ 1;
            As[nxt][acol + 0][arow] = a4.x;
            As[nxt][acol + 1][arow] = a4.y;
            As[nxt][acol + 2][arow] = a4.z;
            As[nxt][acol + 3][arow] = a4.w;
            *(float4*)&Bs[nxt][brow][bcol] = b4;
        }
        __syncthreads();
    }

#pragma unroll
    for (int i = 0; i < 8; i++) {
        float* Cp = C + (row0 + rowb + i) * ldc + col0 + colb;
        *(float4*)(Cp)     = make_float4(acc[i][0], acc[i][1], acc[i][2], acc[i][3]);
        *(float4*)(Cp + 4) = make_float4(acc[i][4], acc[i][5], acc[i][6], acc[i][7]);
    }
}

// Column-wise softmax over the query axis (rows), per key column j.
// Thread-per-column => fully coalesced (columns are the fast axis).
// Scale 1/sqrt(T)=1/32 folded in here.
__global__ void colsoftmax_kernel()
{
    const int z = blockIdx.y;                                  // h*8+b
    const int j = blockIdx.x * blockDim.x + threadIdx.x;       // key column
    float* S = g_S + z * 1048576;
    const float scale = 0.03125f;

    float m = -3.402823e38f;
#pragma unroll 8
    for (int i = 0; i < 1024; ++i) m = fmaxf(m, S[i * 1024 + j]);
    const float mm = m * scale;

    float s = 0.0f;
#pragma unroll 8
    for (int i = 0; i < 1024; ++i) s += expf(S[i * 1024 + j] * scale - mm);
    const float inv = 1.0f / s;

#pragma unroll 8
    for (int i = 0; i < 1024; ++i)
        S[i * 1024 + j] = expf(S[i * 1024 + j] * scale - mm) * inv;
}

extern "C" void kernel_launch(void* const* d_in, const int* in_sizes, int n_in,
                              void* d_out, int out_size)
{
    const float* x  = (const float*)d_in[0];
    const float* WQ = (const float*)d_in[1];
    const float* WK = (const float*)d_in[2];
    const float* WV = (const float*)d_in[3];
    const float* WO = (const float*)d_in[4];
    float* out = (float*)d_out;

    // Stage 0: QKV projections (36 x 8192x768x768)
    gemm_kernel<<<dim3(6, 64, 36), 256>>>(0, x, WQ, WK, WV, WO, out);
    // Stage 1: scores (96 x 1024x1024x768)
    gemm_kernel<<<dim3(8, 8, 96), 256>>>(1, x, WQ, WK, WV, WO, out);
    // Stage 2: column softmax (in place, with 1/32 scaling)
    colsoftmax_kernel<<<dim3(4, 96), 256>>>();
    // Stage 3: Z = A @ V (96 x 1024x768x1024) -> [b][h][t][v]
    gemm_kernel<<<dim3(6, 8, 96), 256>>>(2, x, WQ, WK, WV, WO, out);
    // Stage 4: out = view(Z, 8192x9216) @ WO
    gemm_kernel<<<dim3(6, 64, 1), 256>>>(3, x, WQ, WK, WV, WO, out);
}